// round 11
// baseline (speedup 1.0000x reference)
#include <cuda_runtime.h>

// Problem constants
#define BATCH 4
#define TSEQ  2048
#define SSEQ  2048
#define EMB   512
#define NH    8
#define HD    64
#define BHEADS (BATCH*NH)        // 32
#define MROWS  (BATCH*TSEQ)      // 8192
#define NROWS  (BHEADS*TSEQ)     // 65536 attention rows
#define NSTILE (SSEQ/128)        // 16 s-tiles per row

typedef unsigned long long u64;

// ---------------------------------------------------------------------------
// Packed f32x2 helpers (Blackwell sm_103a). fma.rn.f32x2 does 2 IEEE fp32
// FMAs per instruction -> 2x the FFMA roofline (rt_SMSP=2 either way).
// ---------------------------------------------------------------------------
__device__ __forceinline__ u64 pack_dup(float x) {
    u64 d; unsigned xi = __float_as_uint(x);
    asm("mov.b64 %0, {%1, %2};" : "=l"(d) : "r"(xi), "r"(xi));
    return d;
}
__device__ __forceinline__ void fma2(u64& d, u64 a, u64 b) {
    asm("fma.rn.f32x2 %0, %1, %2, %0;" : "+l"(d) : "l"(a), "l"(b));
}
__device__ __forceinline__ float2 unpack2(u64 v) {
    unsigned lo, hi;
    asm("mov.b64 {%0, %1}, %2;" : "=r"(lo), "=r"(hi) : "l"(v));
    return make_float2(__uint_as_float(lo), __uint_as_float(hi));
}

// ---------------------------------------------------------------------------
// Device scratch (allocation-free rule: static __device__ globals)
// ---------------------------------------------------------------------------
__device__ float  g_q[BHEADS * TSEQ * HD];    // 16 MB
__device__ float  g_k[BHEADS * SSEQ * HD];    // 16 MB
__device__ float  g_v[BHEADS * SSEQ * HD];    // 16 MB
__device__ float  g_att[MROWS * EMB];         // 16 MB
__device__ float2 g_part[NSTILE * NROWS];     // 8 MB  flash partials [stile][row]

// ---------------------------------------------------------------------------
// MUFU-based exp: 1 mul (FMA pipe) + 1 ex2.approx (MUFU pipe, otherwise idle).
// Clamp at -126 makes exp(masked - max) flush to exactly 0.
// ---------------------------------------------------------------------------
__device__ __forceinline__ float fast_exp(float x) {
    float z = fmaxf(x * 1.4426950408889634f, -126.0f);
    float r;
    asm("ex2.approx.f32 %0, %1;" : "=f"(r) : "f"(z));
    return r;
}

// ---------------------------------------------------------------------------
// Shared projection GEMM body: Y = (X @ W + bias) * scale.
// X:[8192,512], W:[512,512]. BM=BN=128, BK=16, 256 thr, 8x8 micro-tile via
// f32x2 packed accumulators, register-staged double buffer, vectorized
// epilogue (bias hoisted, STG.128).
// ---------------------------------------------------------------------------
__device__ __forceinline__ void proj_body(
    const float* __restrict__ X, const float* __restrict__ W,
    const float* __restrict__ bias, float* __restrict__ Y,
    float scale, int headSplit,
    float (*XsT)[16][132], float (*Ws)[16][128])
{
    const int tid = threadIdx.x;
    const int tx = tid & 15, ty = tid >> 4;
    const int n0 = blockIdx.x * 128;
    const int m0 = blockIdx.y * 128;

    const int xr0 = tid >> 2,         xk0 = (tid & 3) * 4;
    const int xr1 = (tid + 256) >> 2, xk1 = ((tid + 256) & 3) * 4;
    const int wk0 = tid >> 5,         wn0 = (tid & 31) * 4;
    const int wk1 = (tid + 256) >> 5, wn1 = ((tid + 256) & 31) * 4;

    u64 acc2[8][4];
    #pragma unroll
    for (int i = 0; i < 8; i++)
        #pragma unroll
        for (int j = 0; j < 4; j++) acc2[i][j] = 0ULL;

    {
        float4 x0 = *(const float4*)&X[(size_t)(m0 + xr0) * 512 + xk0];
        float4 x1 = *(const float4*)&X[(size_t)(m0 + xr1) * 512 + xk1];
        float4 w0 = *(const float4*)&W[(size_t)wk0 * 512 + n0 + wn0];
        float4 w1 = *(const float4*)&W[(size_t)wk1 * 512 + n0 + wn1];
        XsT[0][xk0+0][xr0]=x0.x; XsT[0][xk0+1][xr0]=x0.y; XsT[0][xk0+2][xr0]=x0.z; XsT[0][xk0+3][xr0]=x0.w;
        XsT[0][xk1+0][xr1]=x1.x; XsT[0][xk1+1][xr1]=x1.y; XsT[0][xk1+2][xr1]=x1.z; XsT[0][xk1+3][xr1]=x1.w;
        *(float4*)&Ws[0][wk0][wn0] = w0;
        *(float4*)&Ws[0][wk1][wn1] = w1;
    }
    __syncthreads();

    #pragma unroll 1
    for (int it = 0; it < 32; it++) {
        const int buf = it & 1;
        float4 x0, x1, w0, w1;
        const bool more = (it < 31);
        if (more) {
            int kn = (it + 1) * 16;
            x0 = *(const float4*)&X[(size_t)(m0 + xr0) * 512 + kn + xk0];
            x1 = *(const float4*)&X[(size_t)(m0 + xr1) * 512 + kn + xk1];
            w0 = *(const float4*)&W[(size_t)(kn + wk0) * 512 + n0 + wn0];
            w1 = *(const float4*)&W[(size_t)(kn + wk1) * 512 + n0 + wn1];
        }

        #pragma unroll
        for (int k = 0; k < 16; k++) {
            float4 a0 = *(const float4*)&XsT[buf][k][ty * 4];
            float4 a1 = *(const float4*)&XsT[buf][k][64 + ty * 4];
            ulonglong2 bq0 = *(const ulonglong2*)&Ws[buf][k][tx * 4];
            ulonglong2 bq1 = *(const ulonglong2*)&Ws[buf][k][64 + tx * 4];
            u64 bb[4] = {bq0.x, bq0.y, bq1.x, bq1.y};
            float af[8] = {a0.x,a0.y,a0.z,a0.w,a1.x,a1.y,a1.z,a1.w};
            #pragma unroll
            for (int i = 0; i < 8; i++) {
                u64 ad = pack_dup(af[i]);
                #pragma unroll
                for (int j = 0; j < 4; j++) fma2(acc2[i][j], ad, bb[j]);
            }
        }

        if (more) {
            const int nb = buf ^ 1;
            XsT[nb][xk0+0][xr0]=x0.x; XsT[nb][xk0+1][xr0]=x0.y; XsT[nb][xk0+2][xr0]=x0.z; XsT[nb][xk0+3][xr0]=x0.w;
            XsT[nb][xk1+0][xr1]=x1.x; XsT[nb][xk1+1][xr1]=x1.y; XsT[nb][xk1+2][xr1]=x1.z; XsT[nb][xk1+3][xr1]=x1.w;
            *(float4*)&Ws[nb][wk0][wn0] = w0;
            *(float4*)&Ws[nb][wk1][wn1] = w1;
        }
        __syncthreads();
    }

    const int ng0 = n0 + tx * 4;
    const int ng1 = n0 + 64 + tx * 4;
    const float4 bias0 = *(const float4*)&bias[ng0];
    const float4 bias1 = *(const float4*)&bias[ng1];
    const int h0 = ng0 >> 6, d0 = ng0 & 63;
    const int h1 = ng1 >> 6, d1 = ng1 & 63;

    #pragma unroll
    for (int i = 0; i < 8; i++) {
        int r = (i < 4) ? (ty * 4 + i) : (64 + ty * 4 + (i - 4));
        int m = m0 + r;
        float2 c0 = unpack2(acc2[i][0]);
        float2 c1 = unpack2(acc2[i][1]);
        float2 c2 = unpack2(acc2[i][2]);
        float2 c3 = unpack2(acc2[i][3]);
        float4 v0 = make_float4((c0.x + bias0.x) * scale, (c0.y + bias0.y) * scale,
                                (c1.x + bias0.z) * scale, (c1.y + bias0.w) * scale);
        float4 v1 = make_float4((c2.x + bias1.x) * scale, (c2.y + bias1.y) * scale,
                                (c3.x + bias1.z) * scale, (c3.y + bias1.w) * scale);
        if (headSplit) {
            int b = m >> 11, t = m & 2047;
            *(float4*)&Y[((size_t)((b * NH + h0) * TSEQ) + t) * HD + d0] = v0;
            *(float4*)&Y[((size_t)((b * NH + h1) * TSEQ) + t) * HD + d1] = v1;
        } else {
            *(float4*)&Y[(size_t)m * EMB + ng0] = v0;
            *(float4*)&Y[(size_t)m * EMB + ng1] = v1;
        }
    }
}

// Fused Q/K/V projection: gridDim.z = 3 selects the slice.
__global__ __launch_bounds__(256) void qkv_kernel(
    const float* __restrict__ query, const float* __restrict__ key,
    const float* __restrict__ value,
    const float* __restrict__ Wq, const float* __restrict__ bq,
    const float* __restrict__ Wk, const float* __restrict__ bk,
    const float* __restrict__ Wv, const float* __restrict__ bv,
    float* __restrict__ Yq, float* __restrict__ Yk, float* __restrict__ Yv)
{
    __shared__ __align__(16) float XsT[2][16][132];
    __shared__ __align__(16) float Ws[2][16][128];
    const int z = blockIdx.z;
    const float* X    = (z == 0) ? query : (z == 1) ? key : value;
    const float* W    = (z == 0) ? Wq    : (z == 1) ? Wk  : Wv;
    const float* bias = (z == 0) ? bq    : (z == 1) ? bk  : bv;
    float*       Y    = (z == 0) ? Yq    : (z == 1) ? Yk  : Yv;
    const float scale = (z == 0) ? 0.125f : 1.0f;   // q pre-scaled by Dh^-0.5
    proj_body(X, W, bias, Y, scale, 1, XsT, Ws);
}

// Output projection (plain [8192,512] layout).
__global__ __launch_bounds__(256) void proj_kernel(
    const float* __restrict__ X, const float* __restrict__ W,
    const float* __restrict__ bias, float* __restrict__ Y)
{
    __shared__ __align__(16) float XsT[2][16][132];
    __shared__ __align__(16) float Ws[2][16][128];
    proj_body(X, W, bias, Y, 1.0f, 0, XsT, Ws);
}

// ---------------------------------------------------------------------------
// Scores micro-kernel compute step over one staged 32-k chunk.
// ---------------------------------------------------------------------------
__device__ __forceinline__ void scores_compute_chunk(
    u64 acc2[8][4], float (*QsT)[132], float (*KsT)[132], int tx, int ty)
{
    #pragma unroll 4
    for (int k = 0; k < 32; k++) {
        float4 a0 = *(const float4*)&QsT[k][ty * 4];
        float4 a1 = *(const float4*)&QsT[k][64 + ty * 4];
        ulonglong2 bq0 = *(const ulonglong2*)&KsT[k][tx * 4];
        ulonglong2 bq1 = *(const ulonglong2*)&KsT[k][64 + tx * 4];
        u64 bb[4] = {bq0.x, bq0.y, bq1.x, bq1.y};
        float af[8] = {a0.x,a0.y,a0.z,a0.w,a1.x,a1.y,a1.z,a1.w};
        #pragma unroll
        for (int i = 0; i < 8; i++) {
            u64 ad = pack_dup(af[i]);
            #pragma unroll
            for (int j = 0; j < 4; j++) fma2(acc2[i][j], ad, bb[j]);
        }
    }
}

// ---------------------------------------------------------------------------
// Scores: raw = Q @ K^T with masking, PLUS flash partials (rowmax, sumexp).
// Per (b,h): M=T, N=S, Kdim=64. 128x128 tiles, 2 k-chunks of 32, explicit
// register-staged pipeline: chunk-1 LDGs issue BEFORE chunk-0 compute so the
// mid-kernel memory bubble disappears. Masks cooperatively staged into the
// dead Q/K smem; STG.128 epilogue. kpm prefetched before the mainloop.
// ---------------------------------------------------------------------------
__global__ __launch_bounds__(256) void scores_kernel(
    const float* __restrict__ Q, const float* __restrict__ K,
    const unsigned char* __restrict__ amask,
    const unsigned char* __restrict__ kpm,
    float* __restrict__ attnw, float2* __restrict__ part)
{
    __shared__ __align__(16) float SB[2 * 32 * 132];
    float (*QsT)[132] = (float(*)[132])SB;
    float (*KsT)[132] = (float(*)[132])(SB + 32 * 132);
    unsigned char (*cm)[144] = (unsigned char(*)[144])SB;

    const int tid = threadIdx.x;
    const int tx = tid & 15, ty = tid >> 4;
    const int s0 = blockIdx.x * 128;
    const int t0 = blockIdx.y * 128;
    const int bh = blockIdx.z;
    const int b  = bh >> 3;

    const float* Qb = Q + (size_t)bh * TSEQ * HD;
    const float* Kb = K + (size_t)bh * SSEQ * HD;

    // prefetch kpm chunks used by this thread's two staging rows (8 regs)
    const int mc0 = tid & 7, mc1 = (tid + 256) & 7;   // 16B chunk ids
    uint4 kp0 = *(const uint4*)&kpm[(size_t)b * SSEQ + s0 + mc0 * 16];
    uint4 kp1 = *(const uint4*)&kpm[(size_t)b * SSEQ + s0 + mc1 * 16];

    // staging indices: 4 (row, kv) pairs per thread (1024 float4 total / 256 thr)
    const int lr[4] = { tid >> 3, (tid + 256) >> 3, (tid + 512) >> 3, (tid + 768) >> 3 };
    const int lk[4] = { (tid & 7) * 4, ((tid + 256) & 7) * 4, ((tid + 512) & 7) * 4, ((tid + 768) & 7) * 4 };

    u64 acc2[8][4];
    #pragma unroll
    for (int i = 0; i < 8; i++)
        #pragma unroll
        for (int j = 0; j < 4; j++) acc2[i][j] = 0ULL;

    // ---- stage chunk 0 (k = 0..31) ----
    #pragma unroll
    for (int l = 0; l < 4; l++) {
        float4 v = *(const float4*)&Qb[(size_t)(t0 + lr[l]) * HD + lk[l]];
        QsT[lk[l]+0][lr[l]] = v.x; QsT[lk[l]+1][lr[l]] = v.y;
        QsT[lk[l]+2][lr[l]] = v.z; QsT[lk[l]+3][lr[l]] = v.w;
        float4 w = *(const float4*)&Kb[(size_t)(s0 + lr[l]) * HD + lk[l]];
        KsT[lk[l]+0][lr[l]] = w.x; KsT[lk[l]+1][lr[l]] = w.y;
        KsT[lk[l]+2][lr[l]] = w.z; KsT[lk[l]+3][lr[l]] = w.w;
    }
    __syncthreads();

    // ---- issue chunk-1 LDGs into registers (land during chunk-0 compute) ----
    float4 qpre[4], kpre[4];
    #pragma unroll
    for (int l = 0; l < 4; l++) {
        qpre[l] = *(const float4*)&Qb[(size_t)(t0 + lr[l]) * HD + 32 + lk[l]];
        kpre[l] = *(const float4*)&Kb[(size_t)(s0 + lr[l]) * HD + 32 + lk[l]];
    }

    // ---- compute chunk 0 ----
    scores_compute_chunk(acc2, QsT, KsT, tx, ty);
    __syncthreads();

    // ---- STS chunk 1, compute chunk 1 ----
    #pragma unroll
    for (int l = 0; l < 4; l++) {
        QsT[lk[l]+0][lr[l]] = qpre[l].x; QsT[lk[l]+1][lr[l]] = qpre[l].y;
        QsT[lk[l]+2][lr[l]] = qpre[l].z; QsT[lk[l]+3][lr[l]] = qpre[l].w;
        KsT[lk[l]+0][lr[l]] = kpre[l].x; KsT[lk[l]+1][lr[l]] = kpre[l].y;
        KsT[lk[l]+2][lr[l]] = kpre[l].z; KsT[lk[l]+3][lr[l]] = kpre[l].w;
    }
    __syncthreads();
    scores_compute_chunk(acc2, QsT, KsT, tx, ty);
    __syncthreads();

    // stage combined mask tile: cm[r][c] = amask[t0+r][s0+c] | kpm[b][s0+c]
    {
        int r0 = tid >> 3,           c0 = mc0;
        int r1 = (tid + 256) >> 3,   c1 = mc1;
        uint4 a0m = *(const uint4*)&amask[(size_t)(t0 + r0) * SSEQ + s0 + c0 * 16];
        uint4 a1m = *(const uint4*)&amask[(size_t)(t0 + r1) * SSEQ + s0 + c1 * 16];
        uint4 a2m = *(const uint4*)&amask[(size_t)(t0 + r0 + 64) * SSEQ + s0 + c0 * 16];
        uint4 a3m = *(const uint4*)&amask[(size_t)(t0 + r1 + 64) * SSEQ + s0 + c1 * 16];
        uint4 m0; m0.x = a0m.x | kp0.x; m0.y = a0m.y | kp0.y; m0.z = a0m.z | kp0.z; m0.w = a0m.w | kp0.w;
        uint4 m1; m1.x = a1m.x | kp1.x; m1.y = a1m.y | kp1.y; m1.z = a1m.z | kp1.z; m1.w = a1m.w | kp1.w;
        uint4 m2; m2.x = a2m.x | kp0.x; m2.y = a2m.y | kp0.y; m2.z = a2m.z | kp0.z; m2.w = a2m.w | kp0.w;
        uint4 m3; m3.x = a3m.x | kp1.x; m3.y = a3m.y | kp1.y; m3.z = a3m.z | kp1.z; m3.w = a3m.w | kp1.w;
        *(uint4*)&cm[r0][c0 * 16] = m0;
        *(uint4*)&cm[r1][c1 * 16] = m1;
        *(uint4*)&cm[r0 + 64][c0 * 16] = m2;
        *(uint4*)&cm[r1 + 64][c1 * 16] = m3;
    }
    __syncthreads();

    float accf[8][8];
    #pragma unroll
    for (int i = 0; i < 8; i++)
        #pragma unroll
        for (int jj = 0; jj < 4; jj++) {
            float2 c = unpack2(acc2[i][jj]);
            accf[i][jj*2]   = c.x;
            accf[i][jj*2+1] = c.y;
        }

    const int stile = blockIdx.x;
    #pragma unroll
    for (int i = 0; i < 8; i++) {
        int r = (i < 4) ? (ty * 4 + i) : (64 + ty * 4 + (i - 4));
        int t = t0 + r;
        size_t rowbase = ((size_t)bh * TSEQ + t) * SSEQ;

        uchar4 mk0 = *(const uchar4*)&cm[r][tx * 4];
        uchar4 mk1 = *(const uchar4*)&cm[r][64 + tx * 4];
        unsigned char mb[8] = {mk0.x, mk0.y, mk0.z, mk0.w, mk1.x, mk1.y, mk1.z, mk1.w};

        float vtmp[8];
        float rmax = -3.0e38f;
        #pragma unroll
        for (int j = 0; j < 8; j++) {
            float val = (mb[j] != 0) ? -1e30f : accf[i][j];
            vtmp[j] = val;
            rmax = fmaxf(rmax, val);
        }
        float4 o0 = make_float4(vtmp[0], vtmp[1], vtmp[2], vtmp[3]);
        float4 o1 = make_float4(vtmp[4], vtmp[5], vtmp[6], vtmp[7]);
        *(float4*)&attnw[rowbase + s0 + tx * 4] = o0;
        *(float4*)&attnw[rowbase + s0 + 64 + tx * 4] = o1;

        float rsum = 0.0f;
        #pragma unroll
        for (int j = 0; j < 8; j++) rsum += fast_exp(vtmp[j] - rmax);

        #pragma unroll
        for (int o = 8; o > 0; o >>= 1) {
            float om = __shfl_xor_sync(0xffffffffu, rmax, o);
            float os = __shfl_xor_sync(0xffffffffu, rsum, o);
            float nm = fmaxf(rmax, om);
            rsum = rsum * fast_exp(rmax - nm) + os * fast_exp(om - nm);
            rmax = nm;
        }
        if (tx == 0)
            part[(size_t)stile * NROWS + bh * TSEQ + t] = make_float2(rmax, rsum);
    }
}

__device__ __forceinline__ float4 exp_scale4(float4 v, float2 st) {
    float4 e;
    e.x = fast_exp(v.x - st.x) * st.y;
    e.y = fast_exp(v.y - st.x) * st.y;
    e.z = fast_exp(v.z - st.x) * st.y;
    e.w = fast_exp(v.w - st.x) * st.y;
    return e;
}

// ---------------------------------------------------------------------------
// PV fused with softmax finalize AND stats reduction (all 256 threads:
// 2 threads/row x 8 stiles each, then one 2-way smem combine).
// ---------------------------------------------------------------------------
__global__ __launch_bounds__(256) void pv_kernel(
    float* __restrict__ P, const float* __restrict__ V,
    const float2* __restrict__ part, float* __restrict__ O)
{
    __shared__ __align__(16) float PsT[2][16][132];
    __shared__ __align__(16) float Vs[2][16][64];
    __shared__ float2 sst[128];
    __shared__ float2 stmp[256];

    const int tid = threadIdx.x;
    const int tx = tid & 15, ty = tid >> 4;
    const int t0 = blockIdx.x * 128;
    const int bh = blockIdx.y;

    float* Pb = P + (size_t)bh * TSEQ * SSEQ;
    const float* Vb = V + (size_t)bh * SSEQ * HD;

    // stats: thread tid covers stiles [half*8, half*8+8) of row (tid & 127)
    {
        int rloc = tid & 127;
        int half = tid >> 7;
        int row  = bh * TSEQ + t0 + rloc;
        float m = -3.0e38f, sum = 0.0f;
        #pragma unroll
        for (int s = 0; s < 8; s++) {
            float2 pp = part[(size_t)(half * 8 + s) * NROWS + row];
            float nm = fmaxf(m, pp.x);
            sum = sum * fast_exp(m - nm) + pp.y * fast_exp(pp.x - nm);
            m = nm;
        }
        stmp[tid] = make_float2(m, sum);
    }
    __syncthreads();
    if (tid < 128) {
        float2 a = stmp[tid], c = stmp[tid + 128];
        float nm = fmaxf(a.x, c.x);
        float sum = a.y * fast_exp(a.x - nm) + c.y * fast_exp(c.x - nm);
        sst[tid] = make_float2(nm, 1.0f / sum);
    }
    __syncthreads();

    const int pr0 = tid >> 2,         pk0 = (tid & 3) * 4;
    const int pr1 = (tid + 256) >> 2, pk1 = ((tid + 256) & 3) * 4;
    const int vk  = tid >> 4,         vd  = (tid & 15) * 4;

    const float2 st0 = sst[pr0];
    const float2 st1 = sst[pr1];

    u64 acc2[8][2];
    #pragma unroll
    for (int i = 0; i < 8; i++) { acc2[i][0] = 0ULL; acc2[i][1] = 0ULL; }

    {
        float4 p0 = exp_scale4(*(const float4*)&Pb[(size_t)(t0 + pr0) * SSEQ + pk0], st0);
        float4 p1 = exp_scale4(*(const float4*)&Pb[(size_t)(t0 + pr1) * SSEQ + pk1], st1);
        float4 vv = *(const float4*)&Vb[(size_t)vk * HD + vd];
        *(float4*)&Pb[(size_t)(t0 + pr0) * SSEQ + pk0] = p0;
        *(float4*)&Pb[(size_t)(t0 + pr1) * SSEQ + pk1] = p1;
        PsT[0][pk0+0][pr0]=p0.x; PsT[0][pk0+1][pr0]=p0.y; PsT[0][pk0+2][pr0]=p0.z; PsT[0][pk0+3][pr0]=p0.w;
        PsT[0][pk1+0][pr1]=p1.x; PsT[0][pk1+1][pr1]=p1.y; PsT[0][pk1+2][pr1]=p1.z; PsT[0][pk1+3][pr1]=p1.w;
        *(float4*)&Vs[0][vk][vd] = vv;
    }
    __syncthreads();

    #pragma unroll 1
    for (int it = 0; it < 128; it++) {
        const int buf = it & 1;
        float4 p0, p1, vv;
        const bool more = (it < 127);
        if (more) {
            int kn = (it + 1) * 16;
            p0 = *(const float4*)&Pb[(size_t)(t0 + pr0) * SSEQ + kn + pk0];
            p1 = *(const float4*)&Pb[(size_t)(t0 + pr1) * SSEQ + kn + pk1];
            vv = *(const float4*)&Vb[(size_t)(kn + vk) * HD + vd];
        }

        #pragma unroll
        for (int k = 0; k < 16; k++) {
            float4 a0 = *(const float4*)&PsT[buf][k][ty * 4];
            float4 a1 = *(const float4*)&PsT[buf][k][64 + ty * 4];
            ulonglong2 bq = *(const ulonglong2*)&Vs[buf][k][tx * 4];
            u64 bb[2] = {bq.x, bq.y};
            float af[8] = {a0.x,a0.y,a0.z,a0.w,a1.x,a1.y,a1.z,a1.w};
            #pragma unroll
            for (int i = 0; i < 8; i++) {
                u64 ad = pack_dup(af[i]);
                fma2(acc2[i][0], ad, bb[0]);
                fma2(acc2[i][1], ad, bb[1]);
            }
        }

        if (more) {
            const int nb = buf ^ 1;
            int kn = (it + 1) * 16;
            p0 = exp_scale4(p0, st0);
            p1 = exp_scale4(p1, st1);
            *(float4*)&Pb[(size_t)(t0 + pr0) * SSEQ + kn + pk0] = p0;
            *(float4*)&Pb[(size_t)(t0 + pr1) * SSEQ + kn + pk1] = p1;
            PsT[nb][pk0+0][pr0]=p0.x; PsT[nb][pk0+1][pr0]=p0.y; PsT[nb][pk0+2][pr0]=p0.z; PsT[nb][pk0+3][pr0]=p0.w;
            PsT[nb][pk1+0][pr1]=p1.x; PsT[nb][pk1+1][pr1]=p1.y; PsT[nb][pk1+2][pr1]=p1.z; PsT[nb][pk1+3][pr1]=p1.w;
            *(float4*)&Vs[nb][vk][vd] = vv;
        }
        __syncthreads();
    }

    const int b = bh >> 3, h = bh & 7;
    #pragma unroll
    for (int i = 0; i < 8; i++) {
        int t = t0 + ((i < 4) ? (ty * 4 + i) : (64 + ty * 4 + (i - 4)));
        float2 c0 = unpack2(acc2[i][0]);
        float2 c1 = unpack2(acc2[i][1]);
        float4 o = make_float4(c0.x, c0.y, c1.x, c1.y);
        *(float4*)&O[(size_t)(b * TSEQ + t) * EMB + h * HD + tx * 4] = o;
    }
}

// ---------------------------------------------------------------------------
// Launch: fused QKV proj -> scores(+mask+partials) -> PV(+reduce+finalize)
// -> output proj. Output layout: [output (B*T*E)][attn_weights (B*H*T*S)].
// ---------------------------------------------------------------------------
extern "C" void kernel_launch(void* const* d_in, const int* in_sizes, int n_in,
                              void* d_out, int out_size)
{
    const float* query = (const float*)d_in[0];
    const float* key   = (const float*)d_in[1];
    const float* value = (const float*)d_in[2];
    const unsigned char* kpm   = (const unsigned char*)d_in[3];
    const unsigned char* amask = (const unsigned char*)d_in[4];
    const float* Wq = (const float*)d_in[5];
    const float* bq = (const float*)d_in[6];
    const float* Wk = (const float*)d_in[7];
    const float* bk = (const float*)d_in[8];
    const float* Wv = (const float*)d_in[9];
    const float* bv = (const float*)d_in[10];
    const float* Wo = (const float*)d_in[11];
    const float* bo = (const float*)d_in[12];

    float* out   = (float*)d_out;
    float* attnw = out + (size_t)MROWS * EMB;

    float *pQ, *pK, *pV, *pA;
    float2 *pPart;
    cudaGetSymbolAddress((void**)&pQ, g_q);
    cudaGetSymbolAddress((void**)&pK, g_k);
    cudaGetSymbolAddress((void**)&pV, g_v);
    cudaGetSymbolAddress((void**)&pA, g_att);
    cudaGetSymbolAddress((void**)&pPart, g_part);

    dim3 gQKV(EMB / 128, MROWS / 128, 3);          // (4, 64, 3) = 768 blocks
    qkv_kernel<<<gQKV, 256>>>(query, key, value,
                              Wq, bq, Wk, bk, Wv, bv,
                              pQ, pK, pV);

    dim3 gS(SSEQ / 128, TSEQ / 128, BHEADS);       // (16, 16, 32)
    scores_kernel<<<gS, 256>>>(pQ, pK, amask, kpm, attnw, pPart);

    dim3 gPV(TSEQ / 128, BHEADS);                  // (16, 32)
    pv_kernel<<<gPV, 256>>>(attnw, pV, pPart, pA);

    dim3 gProj(EMB / 128, MROWS / 128);            // (4, 64)
    proj_kernel<<<gProj, 256>>>(pA, Wo, bo, out);
}